// round 12
// baseline (speedup 1.0000x reference)
#include <cuda_runtime.h>
#include <cuda_bf16.h>
#include <math.h>
#include <cstdint>

// Problem dims (fixed by the reference setup_inputs)
#define BB   2
#define NN   1024
#define HG   64            // H*G
#define NBATCH (BB*HG)     // 128 independent GEMM batches
#define NROWS  (BB*NN*HG)  // 131072 SH rows per side
#define KPAD 64            // 48 used (h|h|l or h|l|h), padded to 64 bf16 rows

// bf16 hi/lo operand arrays, [batch][n][KPAD], K-contiguous rows
__device__ __nv_bfloat16 g_Abf[(size_t)NBATCH * NN * KPAD];  // q side (scaled)
__device__ __nv_bfloat16 g_Bbf[(size_t)NBATCH * NN * KPAD];  // k side

// ---------------------------------------------------------------------------
// small PTX helpers
// ---------------------------------------------------------------------------
__device__ __forceinline__ uint32_t smem_u32(const void* p) {
    uint32_t r;
    asm("{ .reg .u64 t; cvta.to.shared.u64 t, %1; cvt.u32.u64 %0, t; }"
        : "=r"(r) : "l"(p));
    return r;
}

__device__ __forceinline__ void cp_async16(uint32_t dst, const void* src) {
    asm volatile("cp.async.cg.shared.global [%0], [%1], 16;"
                 :: "r"(dst), "l"(src) : "memory");
}
#define CP_COMMIT()  asm volatile("cp.async.commit_group;" ::: "memory")
#define CP_WAIT0()   asm volatile("cp.async.wait_group 0;" ::: "memory")

// mma.sync bf16 (m16n8k16, fp32 accum) — portable PTX (compute_103 ok)
__device__ __forceinline__ void mma_bf16(float* d,
                                         uint32_t a0, uint32_t a1,
                                         uint32_t a2, uint32_t a3,
                                         uint32_t b0, uint32_t b1)
{
    asm volatile(
        "mma.sync.aligned.m16n8k16.row.col.f32.bf16.bf16.f32 "
        "{%0,%1,%2,%3}, {%4,%5,%6,%7}, {%8,%9}, {%0,%1,%2,%3};"
        : "+f"(d[0]), "+f"(d[1]), "+f"(d[2]), "+f"(d[3])
        : "r"(a0), "r"(a1), "r"(a2), "r"(a3), "r"(b0), "r"(b1));
}

// B column permutation (verified in R8/R9): actual tile-local col w maps to
// smem row f = bperm(w); thread c = lane&3 then owns contiguous 16-float
// spans of the output row, enabling STG.128 stores.
__device__ __forceinline__ int bperm(int w)
{
    return (w & 0x70) | ((w & 2) << 2) | ((w & 0xC) >> 1) | (w & 1);
}

// ---------------------------------------------------------------------------
// Kernel 1: rotate -> normalize -> SH -> bf16 hi/lo split -> K-padded rows.
//   q side (which=0): cols [h,h,l] of Y/sqrt(15)  -> g_Abf
//   k side (which=1): cols [h,l,h] of Y           -> g_Bbf
// Dot over 48 cols then gives h.h + h.l + l.h  (compensated bf16 product).
// ---------------------------------------------------------------------------
__global__ void sh_expand_kernel(const float* __restrict__ q_in,
                                 const float* __restrict__ k_in,
                                 const float* __restrict__ rq_in,
                                 const float* __restrict__ rk_in)
{
    int gt = blockIdx.x * blockDim.x + threadIdx.x;
    if (gt >= 2 * NROWS) return;
    int which = gt >= NROWS;          // 0 -> q, 1 -> k
    int t = gt - which * NROWS;

    const float* v_in = which ? k_in : q_in;
    const float* r_in = which ? rk_in : rq_in;
    float scale = which ? 1.0f : 0.2581988897471611f;  // 1/sqrt(15)

    int hg = t & (HG - 1);       // h*G + g
    int bn = t >> 6;             // b*N + n
    int b  = bn >> 10;           // /N
    int n  = bn & (NN - 1);

    const float* q = v_in + (size_t)t * 3;
    const float* r = r_in + (size_t)bn * 9;
    float q0 = q[0], q1 = q[1], q2 = q[2];

    float vx = r[0]*q0 + r[1]*q1 + r[2]*q2;
    float vy = r[3]*q0 + r[4]*q1 + r[5]*q2;
    float vz = r[6]*q0 + r[7]*q1 + r[8]*q2;

    float nrm = sqrtf(vx*vx + vy*vy + vz*vz);
    float inv = 1.0f / fmaxf(nrm, 1e-12f);
    float x = vx*inv, y = vy*inv, z = vz*inv;
    float x2 = x*x, y2 = y*y, z2 = z*z;

    const float f1 = 0.4886025119029199f * scale;  // sqrt(3/(4pi))
    const float f2 = 0.6307831305050401f * scale;  // sqrt(5/(4pi))
    const float f3 = 0.7463526651802308f * scale;  // sqrt(7/(4pi))
    const float s3  = 1.7320508075688772f;
    const float s15 = 3.8729833462074170f;
    const float c1  = 0.6123724356957945f;         // sqrt(3/8)
    const float c3  = 0.7905694150420949f;         // sqrt(5/8)

    float yv[15];
    yv[0]  = f1 * x;
    yv[1]  = f1 * y;
    yv[2]  = f1 * z;
    yv[3]  = f2 * (s3 * x * z);
    yv[4]  = f2 * (s3 * x * y);
    yv[5]  = f2 * (y2 - 0.5f * (x2 + z2));
    yv[6]  = f2 * (s3 * y * z);
    yv[7]  = f2 * (0.5f * s3) * (z2 - x2);
    yv[8]  = f3 * (c3 * x * (3.0f * z2 - x2));
    yv[9]  = f3 * (s15 * x * y * z);
    yv[10] = f3 * (c1 * x * (4.0f * y2 - x2 - z2));
    yv[11] = f3 * (0.5f * y * (2.0f * y2 - 3.0f * x2 - 3.0f * z2));
    yv[12] = f3 * (c1 * z * (4.0f * y2 - x2 - z2));
    yv[13] = f3 * (0.5f * s15) * (y * (z2 - x2));
    yv[14] = f3 * (c3 * z * (z2 - 3.0f * x2));

    // hi/lo bf16 split
    unsigned short hb[15], lb[15];
    #pragma unroll
    for (int j = 0; j < 15; j++) {
        __nv_bfloat16 h = __float2bfloat16(yv[j]);
        float hf = __bfloat162float(h);
        __nv_bfloat16 l = __float2bfloat16(yv[j] - hf);
        hb[j] = __bfloat16_as_ushort(h);
        lb[j] = __bfloat16_as_ushort(l);
    }

    // assemble 48 cols: q -> [h|h|l], k -> [h|l|h]; cols 45..63 zero-padded
    unsigned short cols[48];
    #pragma unroll
    for (int j = 0; j < 15; j++) {
        cols[j]      = hb[j];
        cols[15 + j] = which ? lb[j] : hb[j];
        cols[30 + j] = which ? hb[j] : lb[j];
    }
    cols[45] = 0; cols[46] = 0; cols[47] = 0;

    uint32_t u[32];
    #pragma unroll
    for (int i = 0; i < 24; i++)
        u[i] = (uint32_t)cols[2 * i] | ((uint32_t)cols[2 * i + 1] << 16);
    #pragma unroll
    for (int i = 24; i < 32; i++) u[i] = 0;

    __nv_bfloat16* dst = which ? g_Bbf : g_Abf;
    size_t obase = (((size_t)b * HG + hg) * NN + n) * KPAD;
    uint4* o = (uint4*)(dst + obase);
    #pragma unroll
    for (int i = 0; i < 8; i++)
        o[i] = make_uint4(u[4*i], u[4*i+1], u[4*i+2], u[4*i+3]);
}

// ---------------------------------------------------------------------------
// Kernel 2: strip-persistent batched GEMM on HMMA, 3 CTAs/SM target.
// scores[batch, n, m] = sum_{d<48} A[n,d] * B[m,d]   (both bf16, fp32 accum)
// Block = 128(n) x 512(m) strip, 256 threads, 8 tiles of 128x64.
// Warp tile 32x32: acc = 32 regs. A staged once; fragments for k-steps 0,1
// hoisted to registers (16 regs), step 2 loaded inline per tile.
// B tiles (64x48) double-buffered via cp.async, columns permuted per bperm()
// -> STG.128 epilogue. smem pitch 112B, conflict-free.
// ---------------------------------------------------------------------------
#define PITCHB 112    // smem row pitch in bytes (56 bf16)

__global__ void __launch_bounds__(256, 3) score_mma_kernel(float* __restrict__ out)
{
    __shared__ __align__(16) char smA[128 * PITCHB];
    __shared__ __align__(16) char smB[2][64 * PITCHB];

    int batch = blockIdx.z;
    int n0 = blockIdx.y * 128;
    int ms = blockIdx.x * 512;
    int tid = threadIdx.x;

    const uint4* Ag = (const uint4*)(g_Abf + (size_t)batch * NN * KPAD);
    const uint4* Bg = (const uint4*)(g_Bbf + (size_t)batch * NN * KPAD);

    // A staging: 128 rows x 6 chunks = 768 items, 3 per thread.
    // B staging: 64 rows x 6 chunks = 384 items: item tid, plus item 256+tid
    //            for tid < 128.
    int brow0 = tid / 6, bch0 = tid % 6;
    int brow1 = (256 + tid) / 6, bch1 = (256 + tid) % 6;
    int bhalf = (tid < 128);
    uint32_t boff0 = (uint32_t)(bperm(brow0) * PITCHB + bch0 * 16);
    uint32_t boff1 = (uint32_t)(bperm(brow1) * PITCHB + bch1 * 16);
    uint32_t smB_u[2] = { smem_u32(smB[0]), smem_u32(smB[1]) };

    // ---- prologue: cp.async A and B tile 0, then drain ----
    {
        uint32_t smA_u = smem_u32(smA);
        #pragma unroll
        for (int i = 0; i < 3; i++) {
            int idx = tid + i * 256;
            int row = idx / 6, ch = idx % 6;
            cp_async16(smA_u + row * PITCHB + ch * 16,
                       Ag + (size_t)(n0 + row) * 8 + ch);
        }
        cp_async16(smB_u[0] + boff0, Bg + (size_t)(ms + brow0) * 8 + bch0);
        if (bhalf)
            cp_async16(smB_u[0] + boff1, Bg + (size_t)(ms + brow1) * 8 + bch1);
        CP_COMMIT();
        CP_WAIT0();
        __syncthreads();
    }

    int lane = tid & 31;
    int wid  = tid >> 5;
    int g = lane >> 2;            // 0..7
    int c = lane & 3;             // 0..3
    int wrow = (wid & 3) * 32;    // warp row base (n)
    int wcol = (wid >> 2) * 32;   // warp col base within 64-col tile

    // ---- hoist A fragments for k-steps 0,1 (16 regs) ----
    uint32_t af[2][2][4];
    const char* aln0 = smA + (wrow + g) * PITCHB + 4 * c;   // + s*32 bytes
    #pragma unroll
    for (int s = 0; s < 2; s++) {
        #pragma unroll
        for (int mf = 0; mf < 2; mf++) {
            const char* base0 = aln0 + mf * 16 * PITCHB + s * 32;
            const char* base1 = base0 + 8 * PITCHB;
            af[s][mf][0] = *(const uint32_t*)(base0);
            af[s][mf][1] = *(const uint32_t*)(base1);
            af[s][mf][2] = *(const uint32_t*)(base0 + 16);
            af[s][mf][3] = *(const uint32_t*)(base1 + 16);
        }
    }

    float* obase = out + (size_t)batch * NN * NN;

    #pragma unroll 1
    for (int j = 0; j < 8; j++) {
        const char* sB = smB[j & 1];

        // issue async copy of next B tile (overlaps with compute below)
        if (j < 7) {
            uint32_t dstb = smB_u[(j + 1) & 1];
            size_t base = (size_t)(ms + (j + 1) * 64);
            cp_async16(dstb + boff0, Bg + (base + brow0) * 8 + bch0);
            if (bhalf)
                cp_async16(dstb + boff1, Bg + (base + brow1) * 8 + bch1);
            CP_COMMIT();
        }

        // ---- compute 128x64 tile: acc[mf][nf][4], warp part 32x32 ----
        float acc[2][4][4];
        #pragma unroll
        for (int mf = 0; mf < 2; mf++)
            #pragma unroll
            for (int nf = 0; nf < 4; nf++)
                #pragma unroll
                for (int e = 0; e < 4; e++) acc[mf][nf][e] = 0.0f;

        #pragma unroll
        for (int s = 0; s < 3; s++) {
            int koff = s * 32 + 4 * c;   // byte offset of k pair (k = 16s+2c)

            uint32_t a[2][4];
            if (s < 2) {
                #pragma unroll
                for (int mf = 0; mf < 2; mf++)
                    #pragma unroll
                    for (int e = 0; e < 4; e++) a[mf][e] = af[s][mf][e];
            } else {
                #pragma unroll
                for (int mf = 0; mf < 2; mf++) {
                    const char* base0 = aln0 + mf * 16 * PITCHB + 64;
                    const char* base1 = base0 + 8 * PITCHB;
                    a[mf][0] = *(const uint32_t*)(base0);
                    a[mf][1] = *(const uint32_t*)(base1);
                    a[mf][2] = *(const uint32_t*)(base0 + 16);
                    a[mf][3] = *(const uint32_t*)(base1 + 16);
                }
            }

            #pragma unroll
            for (int nf = 0; nf < 4; nf++) {
                const char* bb = sB + (wcol + nf * 8 + g) * PITCHB + koff;
                uint32_t b0 = *(const uint32_t*)(bb);        // col g, k
                uint32_t b1 = *(const uint32_t*)(bb + 16);   // col g, k+8
                mma_bf16(acc[0][nf], a[0][0], a[0][1], a[0][2], a[0][3], b0, b1);
                mma_bf16(acc[1][nf], a[1][0], a[1][1], a[1][2], a[1][3], b0, b1);
            }
        }

        // ---- store tile j: permuted layout -> 8 STG.128 per thread ----
        int mcol = ms + j * 64;
        #pragma unroll
        for (int mf = 0; mf < 2; mf++) {
            #pragma unroll
            for (int r2 = 0; r2 < 2; r2++) {
                float* rp = obase
                          + (size_t)(n0 + wrow + mf * 16 + g + 8 * r2) * NN
                          + mcol + wcol + 4 * c;
                #pragma unroll
                for (int h = 0; h < 2; h++) {
                    float4 v = make_float4(acc[mf][2*h    ][2*r2    ],
                                           acc[mf][2*h    ][2*r2 + 1],
                                           acc[mf][2*h + 1][2*r2    ],
                                           acc[mf][2*h + 1][2*r2 + 1]);
                    __stcs((float4*)(rp + 16 * h), v);
                }
            }
        }

        // ---- drain next tile's copy, flip buffers ----
        if (j < 7) {
            CP_WAIT0();
            __syncthreads();
        }
    }
}

// ---------------------------------------------------------------------------
extern "C" void kernel_launch(void* const* d_in, const int* in_sizes, int n_in,
                              void* d_out, int out_size)
{
    const float* q  = (const float*)d_in[0];
    const float* k  = (const float*)d_in[1];
    const float* rq = (const float*)d_in[2];
    const float* rk = (const float*)d_in[3];
    float* out = (float*)d_out;

    int blocks = (2 * NROWS + 255) / 256;
    sh_expand_kernel<<<blocks, 256>>>(q, k, rq, rk);

    dim3 grid(NN / 512, NN / 128, NBATCH);  // 2 x 8 x 128 = 2048 blocks
    score_mma_kernel<<<grid, 256>>>(out);
}

// round 13
// speedup vs baseline: 1.0411x; 1.0411x over previous
#include <cuda_runtime.h>
#include <cuda_bf16.h>
#include <math.h>
#include <cstdint>

// Problem dims (fixed by the reference setup_inputs)
#define BB   2
#define NN   1024
#define HG   64            // H*G
#define NBATCH (BB*HG)     // 128 independent GEMM batches
#define NROWS  (BB*NN*HG)  // 131072 SH rows per side
#define KPAD 64            // 48 used (h|h|l or h|l|h), padded to 64 bf16 rows

// bf16 hi/lo operand arrays, [batch][n][KPAD], K-contiguous rows
__device__ __nv_bfloat16 g_Abf[(size_t)NBATCH * NN * KPAD];  // q side (scaled)
__device__ __nv_bfloat16 g_Bbf[(size_t)NBATCH * NN * KPAD];  // k side

// ---------------------------------------------------------------------------
// small PTX helpers
// ---------------------------------------------------------------------------
__device__ __forceinline__ uint32_t smem_u32(const void* p) {
    uint32_t r;
    asm("{ .reg .u64 t; cvta.to.shared.u64 t, %1; cvt.u32.u64 %0, t; }"
        : "=r"(r) : "l"(p));
    return r;
}

__device__ __forceinline__ void cp_async16(uint32_t dst, const void* src) {
    asm volatile("cp.async.cg.shared.global [%0], [%1], 16;"
                 :: "r"(dst), "l"(src) : "memory");
}
#define CP_COMMIT()  asm volatile("cp.async.commit_group;" ::: "memory")
#define CP_WAIT(n)   asm volatile("cp.async.wait_group %0;" :: "n"(n) : "memory")

// mma.sync bf16 (m16n8k16, fp32 accum) — portable PTX (compute_103 ok)
__device__ __forceinline__ void mma_bf16(float* d,
                                         uint32_t a0, uint32_t a1,
                                         uint32_t a2, uint32_t a3,
                                         uint32_t b0, uint32_t b1)
{
    asm volatile(
        "mma.sync.aligned.m16n8k16.row.col.f32.bf16.bf16.f32 "
        "{%0,%1,%2,%3}, {%4,%5,%6,%7}, {%8,%9}, {%0,%1,%2,%3};"
        : "+f"(d[0]), "+f"(d[1]), "+f"(d[2]), "+f"(d[3])
        : "r"(a0), "r"(a1), "r"(a2), "r"(a3), "r"(b0), "r"(b1));
}

// B column permutation (verified in R8/R9): actual tile-local col w maps to
// smem row f = bperm(w); thread c = lane&3 then owns contiguous 16-float
// spans of the output row, enabling STG.128 stores.
__device__ __forceinline__ int bperm(int w)
{
    return (w & 0x70) | ((w & 2) << 2) | ((w & 0xC) >> 1) | (w & 1);
}

// ---------------------------------------------------------------------------
// Kernel 1: rotate -> normalize -> SH -> bf16 hi/lo split -> K-padded rows.
//   q side (which=0): cols [h,h,l] of Y/sqrt(15)  -> g_Abf
//   k side (which=1): cols [h,l,h] of Y           -> g_Bbf
// Dot over 48 cols then gives h.h + h.l + l.h  (compensated bf16 product).
// ---------------------------------------------------------------------------
__global__ void sh_expand_kernel(const float* __restrict__ q_in,
                                 const float* __restrict__ k_in,
                                 const float* __restrict__ rq_in,
                                 const float* __restrict__ rk_in)
{
    int gt = blockIdx.x * blockDim.x + threadIdx.x;
    if (gt >= 2 * NROWS) return;
    int which = gt >= NROWS;          // 0 -> q, 1 -> k
    int t = gt - which * NROWS;

    const float* v_in = which ? k_in : q_in;
    const float* r_in = which ? rk_in : rq_in;
    float scale = which ? 1.0f : 0.2581988897471611f;  // 1/sqrt(15)

    int hg = t & (HG - 1);       // h*G + g
    int bn = t >> 6;             // b*N + n
    int b  = bn >> 10;           // /N
    int n  = bn & (NN - 1);

    const float* q = v_in + (size_t)t * 3;
    const float* r = r_in + (size_t)bn * 9;
    float q0 = q[0], q1 = q[1], q2 = q[2];

    float vx = r[0]*q0 + r[1]*q1 + r[2]*q2;
    float vy = r[3]*q0 + r[4]*q1 + r[5]*q2;
    float vz = r[6]*q0 + r[7]*q1 + r[8]*q2;

    float nrm = sqrtf(vx*vx + vy*vy + vz*vz);
    float inv = 1.0f / fmaxf(nrm, 1e-12f);
    float x = vx*inv, y = vy*inv, z = vz*inv;
    float x2 = x*x, y2 = y*y, z2 = z*z;

    const float f1 = 0.4886025119029199f * scale;  // sqrt(3/(4pi))
    const float f2 = 0.6307831305050401f * scale;  // sqrt(5/(4pi))
    const float f3 = 0.7463526651802308f * scale;  // sqrt(7/(4pi))
    const float s3  = 1.7320508075688772f;
    const float s15 = 3.8729833462074170f;
    const float c1  = 0.6123724356957945f;         // sqrt(3/8)
    const float c3  = 0.7905694150420949f;         // sqrt(5/8)

    float yv[15];
    yv[0]  = f1 * x;
    yv[1]  = f1 * y;
    yv[2]  = f1 * z;
    yv[3]  = f2 * (s3 * x * z);
    yv[4]  = f2 * (s3 * x * y);
    yv[5]  = f2 * (y2 - 0.5f * (x2 + z2));
    yv[6]  = f2 * (s3 * y * z);
    yv[7]  = f2 * (0.5f * s3) * (z2 - x2);
    yv[8]  = f3 * (c3 * x * (3.0f * z2 - x2));
    yv[9]  = f3 * (s15 * x * y * z);
    yv[10] = f3 * (c1 * x * (4.0f * y2 - x2 - z2));
    yv[11] = f3 * (0.5f * y * (2.0f * y2 - 3.0f * x2 - 3.0f * z2));
    yv[12] = f3 * (c1 * z * (4.0f * y2 - x2 - z2));
    yv[13] = f3 * (0.5f * s15) * (y * (z2 - x2));
    yv[14] = f3 * (c3 * z * (z2 - 3.0f * x2));

    // hi/lo bf16 split
    unsigned short hb[15], lb[15];
    #pragma unroll
    for (int j = 0; j < 15; j++) {
        __nv_bfloat16 h = __float2bfloat16(yv[j]);
        float hf = __bfloat162float(h);
        __nv_bfloat16 l = __float2bfloat16(yv[j] - hf);
        hb[j] = __bfloat16_as_ushort(h);
        lb[j] = __bfloat16_as_ushort(l);
    }

    // assemble 48 cols: q -> [h|h|l], k -> [h|l|h]; cols 45..63 zero-padded
    unsigned short cols[48];
    #pragma unroll
    for (int j = 0; j < 15; j++) {
        cols[j]      = hb[j];
        cols[15 + j] = which ? lb[j] : hb[j];
        cols[30 + j] = which ? hb[j] : lb[j];
    }
    cols[45] = 0; cols[46] = 0; cols[47] = 0;

    uint32_t u[32];
    #pragma unroll
    for (int i = 0; i < 24; i++)
        u[i] = (uint32_t)cols[2 * i] | ((uint32_t)cols[2 * i + 1] << 16);
    #pragma unroll
    for (int i = 24; i < 32; i++) u[i] = 0;

    __nv_bfloat16* dst = which ? g_Bbf : g_Abf;
    size_t obase = (((size_t)b * HG + hg) * NN + n) * KPAD;
    uint4* o = (uint4*)(dst + obase);
    #pragma unroll
    for (int i = 0; i < 8; i++)
        o[i] = make_uint4(u[4*i], u[4*i+1], u[4*i+2], u[4*i+3]);
}

// ---------------------------------------------------------------------------
// Kernel 2: strip-persistent batched GEMM on HMMA, deep cp.async pipeline.
// scores[batch, n, m] = sum_{d<48} A[n,d] * B[m,d]   (both bf16, fp32 accum)
// Block = 128(n) x 512(m) strip, 256 threads, 8 tiles of 128x64.
// Warp tile 32x32 (acc 32 regs); A staged once, k-steps 0,1 hoisted to regs.
// B ring: 4 buffers, 3 tiles in flight (wait_group 2) — copy latency covered
// by ~2 tiles of compute+stores, so the per-tile barrier is nearly free.
// B columns permuted per bperm() -> STG.128 epilogue. Pitch 112B, no conflicts.
// Group schedule: prologue commits groups 0..2 (A rides group 0); every loop
// iteration commits exactly one group (empty for j>=5), so at the top of
// iteration j, groups 0..j are complete after wait_group 2.
// ---------------------------------------------------------------------------
#define PITCHB 112    // smem row pitch in bytes (56 bf16)
#define NSTAGE 4

__global__ void __launch_bounds__(256, 3) score_mma_kernel(float* __restrict__ out)
{
    __shared__ __align__(16) char smA[128 * PITCHB];
    __shared__ __align__(16) char smB[NSTAGE][64 * PITCHB];

    int batch = blockIdx.z;
    int n0 = blockIdx.y * 128;
    int ms = blockIdx.x * 512;
    int tid = threadIdx.x;

    const uint4* Ag = (const uint4*)(g_Abf + (size_t)batch * NN * KPAD);
    const uint4* Bg = (const uint4*)(g_Bbf + (size_t)batch * NN * KPAD);

    // B staging: 64 rows x 6 chunks = 384 items: item tid, plus item 256+tid
    //            for tid < 128.
    int brow0 = tid / 6, bch0 = tid % 6;
    int brow1 = (256 + tid) / 6, bch1 = (256 + tid) % 6;
    int bhalf = (tid < 128);
    uint32_t boff0 = (uint32_t)(bperm(brow0) * PITCHB + bch0 * 16);
    uint32_t boff1 = (uint32_t)(bperm(brow1) * PITCHB + bch1 * 16);
    uint32_t smB_u[NSTAGE];
    #pragma unroll
    for (int i = 0; i < NSTAGE; i++) smB_u[i] = smem_u32(smB[i]);

    // ---- prologue: group 0 = A + B tile 0; groups 1,2 = B tiles 1,2 ----
    {
        uint32_t smA_u = smem_u32(smA);
        #pragma unroll
        for (int i = 0; i < 3; i++) {
            int idx = tid + i * 256;
            int row = idx / 6, ch = idx % 6;
            cp_async16(smA_u + row * PITCHB + ch * 16,
                       Ag + (size_t)(n0 + row) * 8 + ch);
        }
        cp_async16(smB_u[0] + boff0, Bg + (size_t)(ms + brow0) * 8 + bch0);
        if (bhalf)
            cp_async16(smB_u[0] + boff1, Bg + (size_t)(ms + brow1) * 8 + bch1);
        CP_COMMIT();
        #pragma unroll
        for (int tnext = 1; tnext <= 2; tnext++) {
            size_t base = (size_t)(ms + tnext * 64);
            cp_async16(smB_u[tnext] + boff0, Bg + (base + brow0) * 8 + bch0);
            if (bhalf)
                cp_async16(smB_u[tnext] + boff1, Bg + (base + brow1) * 8 + bch1);
            CP_COMMIT();
        }
    }

    // wait for group 0 (A + B0): <=2 pending of {0,1,2}
    CP_WAIT(2);
    __syncthreads();

    int lane = tid & 31;
    int wid  = tid >> 5;
    int g = lane >> 2;            // 0..7
    int c = lane & 3;             // 0..3
    int wrow = (wid & 3) * 32;    // warp row base (n)
    int wcol = (wid >> 2) * 32;   // warp col base within 64-col tile

    // ---- hoist A fragments for k-steps 0,1 (16 regs) ----
    uint32_t af[2][2][4];
    const char* aln0 = smA + (wrow + g) * PITCHB + 4 * c;   // + s*32 bytes
    #pragma unroll
    for (int s = 0; s < 2; s++) {
        #pragma unroll
        for (int mf = 0; mf < 2; mf++) {
            const char* base0 = aln0 + mf * 16 * PITCHB + s * 32;
            const char* base1 = base0 + 8 * PITCHB;
            af[s][mf][0] = *(const uint32_t*)(base0);
            af[s][mf][1] = *(const uint32_t*)(base1);
            af[s][mf][2] = *(const uint32_t*)(base0 + 16);
            af[s][mf][3] = *(const uint32_t*)(base1 + 16);
        }
    }

    float* obase = out + (size_t)batch * NN * NN;

    #pragma unroll 1
    for (int j = 0; j < 8; j++) {
        if (j > 0) {
            CP_WAIT(2);           // tile j's group complete
            __syncthreads();      // visible to all warps; buffer (j+3)&3 free
        }

        // issue copy for tile j+3 (one group per iteration; empty if j>=5)
        if (j < 5) {
            uint32_t dstb = smB_u[(j + 3) & (NSTAGE - 1)];
            size_t base = (size_t)(ms + (j + 3) * 64);
            cp_async16(dstb + boff0, Bg + (base + brow0) * 8 + bch0);
            if (bhalf)
                cp_async16(dstb + boff1, Bg + (base + brow1) * 8 + bch1);
        }
        CP_COMMIT();

        const char* sB = smB[j & (NSTAGE - 1)];

        // ---- compute 128x64 tile: acc[mf][nf][4], warp part 32x32 ----
        float acc[2][4][4];
        #pragma unroll
        for (int mf = 0; mf < 2; mf++)
            #pragma unroll
            for (int nf = 0; nf < 4; nf++)
                #pragma unroll
                for (int e = 0; e < 4; e++) acc[mf][nf][e] = 0.0f;

        #pragma unroll
        for (int s = 0; s < 3; s++) {
            int koff = s * 32 + 4 * c;   // byte offset of k pair (k = 16s+2c)

            uint32_t a[2][4];
            if (s < 2) {
                #pragma unroll
                for (int mf = 0; mf < 2; mf++)
                    #pragma unroll
                    for (int e = 0; e < 4; e++) a[mf][e] = af[s][mf][e];
            } else {
                #pragma unroll
                for (int mf = 0; mf < 2; mf++) {
                    const char* base0 = aln0 + mf * 16 * PITCHB + 64;
                    const char* base1 = base0 + 8 * PITCHB;
                    a[mf][0] = *(const uint32_t*)(base0);
                    a[mf][1] = *(const uint32_t*)(base1);
                    a[mf][2] = *(const uint32_t*)(base0 + 16);
                    a[mf][3] = *(const uint32_t*)(base1 + 16);
                }
            }

            #pragma unroll
            for (int nf = 0; nf < 4; nf++) {
                const char* bb = sB + (wcol + nf * 8 + g) * PITCHB + koff;
                uint32_t b0 = *(const uint32_t*)(bb);        // col g, k
                uint32_t b1 = *(const uint32_t*)(bb + 16);   // col g, k+8
                mma_bf16(acc[0][nf], a[0][0], a[0][1], a[0][2], a[0][3], b0, b1);
                mma_bf16(acc[1][nf], a[1][0], a[1][1], a[1][2], a[1][3], b0, b1);
            }
        }

        // ---- store tile j: permuted layout -> 8 STG.128 per thread ----
        int mcol = ms + j * 64;
        #pragma unroll
        for (int mf = 0; mf < 2; mf++) {
            #pragma unroll
            for (int r2 = 0; r2 < 2; r2++) {
                float* rp = obase
                          + (size_t)(n0 + wrow + mf * 16 + g + 8 * r2) * NN
                          + mcol + wcol + 4 * c;
                #pragma unroll
                for (int h = 0; h < 2; h++) {
                    float4 v = make_float4(acc[mf][2*h    ][2*r2    ],
                                           acc[mf][2*h    ][2*r2 + 1],
                                           acc[mf][2*h + 1][2*r2    ],
                                           acc[mf][2*h + 1][2*r2 + 1]);
                    __stcs((float4*)(rp + 16 * h), v);
                }
            }
        }
    }
}

// ---------------------------------------------------------------------------
extern "C" void kernel_launch(void* const* d_in, const int* in_sizes, int n_in,
                              void* d_out, int out_size)
{
    const float* q  = (const float*)d_in[0];
    const float* k  = (const float*)d_in[1];
    const float* rq = (const float*)d_in[2];
    const float* rk = (const float*)d_in[3];
    float* out = (float*)d_out;

    int blocks = (2 * NROWS + 255) / 256;
    sh_expand_kernel<<<blocks, 256>>>(q, k, rq, rk);

    dim3 grid(NN / 512, NN / 128, NBATCH);  // 2 x 8 x 128 = 2048 blocks
    score_mma_kernel<<<grid, 256>>>(out);
}